// round 15
// baseline (speedup 1.0000x reference)
#include <cuda_runtime.h>
#include <cuda_fp16.h>
#include <cstdint>

// ---------------- problem constants ----------------
#define BROWS 4096
#define NOUT  4096
#define KTOT  4122
#define KPAD  4160            // 65 * 64

#define OFF_CD4 262
#define OFF_CD3 524
#define OFF_CD2 1042
#define OFF_CD1 2071

// GEMM tiling: 32x32 tiles of 128x128; first 888 = 3 exact waves (296/wave),
// last 136 tiles split into 272 half-tiles (64x128) -> one short tail wave.
#define FULL_TILES 888

// ---------------- scratch (device globals; no allocs allowed) ----------------
__device__ __half g_C[(size_t)BROWS * KPAD];   // coeffs [M, K] row-major fp16
__device__ __half g_B[(size_t)KPAD * NOUT];    // stacked bases [K, N] row-major fp16

__constant__ float c_lo[8] = {
    -0.010597401784997278f,  0.032883011666982945f,  0.030841381835986965f,
    -0.18703481171888114f,  -0.02798376941698385f,   0.6308807679295904f,
     0.7148465705525415f,    0.23037781330885523f };
__constant__ float c_hi[8] = {
    -0.23037781330885523f,   0.7148465705525415f,   -0.6308807679295904f,
    -0.02798376941698385f,   0.18703481171888114f,   0.030841381835986965f,
    -0.032883011666982945f, -0.010597401784997278f };

// ---------------- fused DWT: all 4 db4 levels for one row, in smem ----------------
// pywt 'symmetric': out[j] = sum_m filt[m] * E[8+2j-m],
//   E[i] = a[6-i] (i<7), a[i-7] (i<Nin+7), a[2*Nin+6-i] otherwise.
__global__ void __launch_bounds__(256)
dwt_kernel(const float* __restrict__ x, __half* __restrict__ C)
{
    __shared__ __align__(16) float bufA[4096];
    __shared__ __align__(16) float bufB[2051];

    const int row = blockIdx.x;
    const int tid = threadIdx.x;
    const float* xr = x + (size_t)row * 4096;
    __half* Crow = C + (size_t)row * KPAD;

    const float4* x4 = (const float4*)xr;
    float4* bA4 = (float4*)bufA;
#pragma unroll
    for (int i = 0; i < 4; i++) bA4[tid + i * 256] = x4[tid + i * 256];

    for (int c = KTOT + tid; c < KPAD; c += 256) Crow[c] = __float2half_rn(0.f);
    __syncthreads();

    const int nin[4]  = {4096, 2051, 1029, 518};
    const int nout[4] = {2051, 1029, 518, 262};
    const int offD[4] = {OFF_CD1, OFF_CD2, OFF_CD3, OFF_CD4};

    float* src = bufA;
    float* dst = bufB;
#pragma unroll 1
    for (int lv = 0; lv < 4; lv++) {
        const int Nin = nin[lv], Nout = nout[lv];
        const int jIntHi = (Nin - 2) >> 1;
        for (int j = tid; j < Nout; j += 256) {
            float sLo = 0.f, sHi = 0.f;
            if (j >= 4 && j <= jIntHi) {
                const float2* q = (const float2*)(src + 2 * j - 6);
                const float2 w3 = q[3], w2 = q[2], w1 = q[1], w0 = q[0];
                sLo = fmaf(c_lo[0], w3.y, sLo); sHi = fmaf(c_hi[0], w3.y, sHi);
                sLo = fmaf(c_lo[1], w3.x, sLo); sHi = fmaf(c_hi[1], w3.x, sHi);
                sLo = fmaf(c_lo[2], w2.y, sLo); sHi = fmaf(c_hi[2], w2.y, sHi);
                sLo = fmaf(c_lo[3], w2.x, sLo); sHi = fmaf(c_hi[3], w2.x, sHi);
                sLo = fmaf(c_lo[4], w1.y, sLo); sHi = fmaf(c_hi[4], w1.y, sHi);
                sLo = fmaf(c_lo[5], w1.x, sLo); sHi = fmaf(c_hi[5], w1.x, sHi);
                sLo = fmaf(c_lo[6], w0.y, sLo); sHi = fmaf(c_hi[6], w0.y, sHi);
                sLo = fmaf(c_lo[7], w0.x, sLo); sHi = fmaf(c_hi[7], w0.x, sHi);
            } else {
#pragma unroll
                for (int m = 0; m < 8; m++) {
                    const int i = 8 + 2 * j - m;
                    int idx;
                    if (i < 7)            idx = 6 - i;
                    else if (i < Nin + 7) idx = i - 7;
                    else                  idx = 2 * Nin + 6 - i;
                    const float v = src[idx];
                    sLo = fmaf(c_lo[m], v, sLo);
                    sHi = fmaf(c_hi[m], v, sHi);
                }
            }
            Crow[offD[lv] + j] = __float2half_rn(sHi);
            if (lv < 3) dst[j] = sLo;
            else        Crow[j] = __float2half_rn(sLo);   // cA4 at col 0
        }
        __syncthreads();
        float* tmp = src; src = dst; dst = tmp;
    }
}

// ---------------- pack bases: one K-row of Bh per block ----------------
__global__ void __launch_bounds__(256)
pack_kernel(const float* __restrict__ b0, const float* __restrict__ b1,
            const float* __restrict__ b2, const float* __restrict__ b3,
            const float* __restrict__ b4, __half* __restrict__ Bh)
{
    const int k   = blockIdx.x;            // 0..KPAD-1
    const int tid = threadIdx.x;

    const float* src = nullptr; int r = 0;
    if      (k < OFF_CD4) { src = b0; r = k; }
    else if (k < OFF_CD3) { src = b1; r = k - OFF_CD4; }
    else if (k < OFF_CD2) { src = b2; r = k - OFF_CD3; }
    else if (k < OFF_CD1) { src = b3; r = k - OFF_CD2; }
    else if (k < KTOT)    { src = b4; r = k - OFF_CD1; }

    __half* dstRow = Bh + (size_t)k * NOUT;
    if (src) {
        const float4* srow = (const float4*)(src + (size_t)r * NOUT);
        float4 v[4];
#pragma unroll
        for (int i = 0; i < 4; i++) v[i] = srow[tid + i * 256];
#pragma unroll
        for (int i = 0; i < 4; i++) {
            __half2 h[2];
            h[0] = __floats2half2_rn(v[i].x, v[i].y);
            h[1] = __floats2half2_rn(v[i].z, v[i].w);
            *(uint64_t*)(dstRow + (tid + i * 256) * 4) = *(uint64_t*)h;
        }
    } else {
#pragma unroll
        for (int i = 0; i < 4; i++)
            *(uint64_t*)(dstRow + (tid + i * 256) * 4) = 0ull;
    }
}

// ---------------- GEMM: [4096,4160] x [4160,4096] fp16 -> fp32 ----------------
// mma.sync.m16n8k16 + ldmatrix + 3-stage cp.async, BK=64, 2 CTAs/SM.
// Templated on MI (m-subtiles per warp): MI=4 -> BM=128 (main), MI=2 -> BM=64 (tail).
#define BN 128
#define BK 64
#define STAGES 3
#define B_STAGE_BYTES 16384      // 64 rows x 128 halves (256B rows)

__device__ __forceinline__ uint32_t aswz(int r, int chunk) {
    return (uint32_t)(r * 128 + ((chunk ^ (r & 7)) << 4));
}
__device__ __forceinline__ uint32_t bswz(int r, int chunk) {
    return (uint32_t)(r * 256 + (((chunk & 8) | ((chunk ^ r) & 7)) << 4));
}

__device__ __forceinline__ void cp16(uint32_t saddr, const void* gaddr) {
    asm volatile("cp.async.cg.shared.global [%0], [%1], 16;\n" :: "r"(saddr), "l"(gaddr));
}
__device__ __forceinline__ void ldsm4(uint32_t* r, uint32_t addr) {
    asm volatile("ldmatrix.sync.aligned.m8n8.x4.shared.b16 {%0,%1,%2,%3}, [%4];"
                 : "=r"(r[0]), "=r"(r[1]), "=r"(r[2]), "=r"(r[3]) : "r"(addr));
}
__device__ __forceinline__ void ldsm4t(uint32_t* r, uint32_t addr) {
    asm volatile("ldmatrix.sync.aligned.m8n8.x4.trans.shared.b16 {%0,%1,%2,%3}, [%4];"
                 : "=r"(r[0]), "=r"(r[1]), "=r"(r[2]), "=r"(r[3]) : "r"(addr));
}
__device__ __forceinline__ void mma16816(float* c, const uint32_t* a, uint32_t b0, uint32_t b1) {
    asm volatile("mma.sync.aligned.m16n8k16.row.col.f32.f16.f16.f32 "
                 "{%0,%1,%2,%3}, {%4,%5,%6,%7}, {%8,%9}, {%0,%1,%2,%3};"
                 : "+f"(c[0]), "+f"(c[1]), "+f"(c[2]), "+f"(c[3])
                 : "r"(a[0]), "r"(a[1]), "r"(a[2]), "r"(a[3]), "r"(b0), "r"(b1));
}

template<int MI>            // BM = MI*32; warp m-extent = MI*16
__global__ void __launch_bounds__(256, 2)
gemm_tmpl(const __half* __restrict__ A, const __half* __restrict__ Bm,
          float* __restrict__ Cout)
{
    constexpr int K = KPAD, N = NOUT;
    constexpr int BM = MI * 32;
    constexpr int A_STAGE_BYTES = BM * 128;                   // BM rows x 128B
    constexpr int STAGE_BYTES   = A_STAGE_BYTES + B_STAGE_BYTES;

    extern __shared__ char smem[];
    const uint32_t sbase = (uint32_t)__cvta_generic_to_shared(smem);

    const int tid = threadIdx.x;
    const int wid = tid >> 5, lid = tid & 31;
    const int wm  = wid & 1;
    const int wn  = wid >> 1;

    int rowBase, colBase;
    if (MI == 4) {
        rowBase = (blockIdx.x >> 5) * 128;          // tiles 0..FULL_TILES-1
        colBase = (blockIdx.x & 31) * 128;
    } else {
        const int t = FULL_TILES + (blockIdx.x >> 1);   // tiles FULL_TILES..1023
        rowBase = (t >> 5) * 128 + (blockIdx.x & 1) * 64;
        colBase = (t & 31) * 128;
    }

    const int l15 = lid & 15, lc = lid >> 4;

    // ---- loader geometry ----
    // A: BM*8 int4/stage -> MI per thread
    int aR[MI]; uint32_t aS[MI];
#pragma unroll
    for (int i = 0; i < MI; i++) {
        const int idx = i * 256 + tid;
        aR[i] = idx >> 3;
        aS[i] = aswz(aR[i], idx & 7);
    }
    // B: 1024 int4/stage -> 4 per thread
    int bR[4]; uint32_t bS[4];
#pragma unroll
    for (int i = 0; i < 4; i++) {
        const int idx = i * 256 + tid;
        bR[i] = idx >> 4;
        bS[i] = bswz(bR[i], idx & 15);
    }

    const __half* Ag = A + (size_t)rowBase * K;
    const __half* Bg = Bm + colBase;

    uint32_t aBase[MI]; int aX[MI];
#pragma unroll
    for (int i = 0; i < MI; i++) {
        const int r = wm * (MI * 16) + i * 16 + l15;
        aBase[i] = (uint32_t)(r * 128);
        aX[i] = r & 7;
    }
    int bChunk[2] = { wn * 4 + 0 * 2 + lc, wn * 4 + 1 * 2 + lc };

    auto issue_stage = [&](int t, int slot) {
        const int kb = t * BK;
        const uint32_t sa = sbase + slot * STAGE_BYTES;
        const uint32_t sb = sa + A_STAGE_BYTES;
#pragma unroll
        for (int i = 0; i < MI; i++) {
            const int idx = i * 256 + tid;
            cp16(sa + aS[i], Ag + (size_t)aR[i] * K + kb + (idx & 7) * 8);
        }
#pragma unroll
        for (int i = 0; i < 4; i++) {
            const int idx = i * 256 + tid;
            cp16(sb + bS[i], Bg + (size_t)(kb + bR[i]) * N + (idx & 15) * 8);
        }
        asm volatile("cp.async.commit_group;\n" ::: "memory");
    };

    float acc[MI][4][4];
#pragma unroll
    for (int i = 0; i < MI; i++)
#pragma unroll
        for (int j = 0; j < 4; j++)
#pragma unroll
            for (int q = 0; q < 4; q++) acc[i][j][q] = 0.f;

    constexpr int NT = K / BK;    // 65
    issue_stage(0, 0);
    issue_stage(1, 1);

    int cs = 0, ps = 2;
    for (int t = 0; t < NT; t++) {
        asm volatile("cp.async.wait_group 1;\n" ::: "memory");
        __syncthreads();
        if (t + 2 < NT) issue_stage(t + 2, ps);

        const uint32_t sa = sbase + cs * STAGE_BYTES;
        const uint32_t sb = sa + A_STAGE_BYTES;

#pragma unroll
        for (int ks = 0; ks < 4; ks++) {
            uint32_t af[MI][4], bf[2][4];
#pragma unroll
            for (int i = 0; i < MI; i++)
                ldsm4(af[i], sa + aBase[i] + (uint32_t)((((ks * 2 + lc) ^ aX[i]) << 4)));
#pragma unroll
            for (int g = 0; g < 2; g++) {
                const int r = ks * 16 + l15;
                ldsm4t(bf[g], sb + (uint32_t)(r * 256 +
                        (((bChunk[g] & 8) | ((bChunk[g] ^ r) & 7)) << 4)));
            }
#pragma unroll
            for (int i = 0; i < MI; i++)
#pragma unroll
                for (int j = 0; j < 4; j++)
                    mma16816(acc[i][j], af[i], bf[j >> 1][(j & 1) * 2],
                             bf[j >> 1][(j & 1) * 2 + 1]);
        }
        cs = (cs == STAGES - 1) ? 0 : cs + 1;
        ps = (ps == STAGES - 1) ? 0 : ps + 1;
    }

    // ---- epilogue: streaming stores (keep A/B in L2) ----
    const int er = lid >> 2, ec = (lid & 3) * 2;
#pragma unroll
    for (int i = 0; i < MI; i++) {
        const int row0 = rowBase + wm * (MI * 16) + i * 16 + er;
#pragma unroll
        for (int j = 0; j < 4; j++) {
            const int col = colBase + wn * 32 + j * 8 + ec;
            float2* p0 = (float2*)(Cout + (size_t)row0 * N + col);
            float2* p1 = (float2*)(Cout + (size_t)(row0 + 8) * N + col);
            __stcs(p0, make_float2(acc[i][j][0], acc[i][j][1]));
            __stcs(p1, make_float2(acc[i][j][2], acc[i][j][3]));
        }
    }
}

#define SMEM4 (STAGES * (128 * 128 + B_STAGE_BYTES))   // 98304
#define SMEM2 (STAGES * (64 * 128  + B_STAGE_BYTES))   // 73728

// ---------------- launch ----------------
extern "C" void kernel_launch(void* const* d_in, const int* in_sizes, int n_in,
                              void* d_out, int out_size)
{
    const float* x  = (const float*)d_in[0];
    const float* b0 = (const float*)d_in[1];
    const float* b1 = (const float*)d_in[2];
    const float* b2 = (const float*)d_in[3];
    const float* b3 = (const float*)d_in[4];
    const float* b4 = (const float*)d_in[5];
    float* out = (float*)d_out;

    __half *Cm, *Bm;
    cudaGetSymbolAddress((void**)&Cm, g_C);
    cudaGetSymbolAddress((void**)&Bm, g_B);

    cudaFuncSetAttribute(gemm_tmpl<4>,
                         cudaFuncAttributeMaxDynamicSharedMemorySize, SMEM4);
    cudaFuncSetAttribute(gemm_tmpl<2>,
                         cudaFuncAttributeMaxDynamicSharedMemorySize, SMEM2);

    // prologue: pack forked to a side stream (harmless), DWT on main
    cudaStream_t s2 = nullptr;
    cudaEvent_t eF = nullptr, eJ = nullptr;
    bool forked =
        (cudaStreamCreateWithFlags(&s2, cudaStreamNonBlocking) == cudaSuccess) &&
        (cudaEventCreateWithFlags(&eF, cudaEventDisableTiming) == cudaSuccess) &&
        (cudaEventCreateWithFlags(&eJ, cudaEventDisableTiming) == cudaSuccess) &&
        (cudaEventRecord(eF, 0) == cudaSuccess) &&
        (cudaStreamWaitEvent(s2, eF, 0) == cudaSuccess);

    if (forked) {
        pack_kernel<<<KPAD, 256, 0, s2>>>(b0, b1, b2, b3, b4, Bm);
        dwt_kernel<<<BROWS, 256>>>(x, Cm);
        cudaEventRecord(eJ, s2);
        cudaStreamWaitEvent(0, eJ, 0);
    } else {
        pack_kernel<<<KPAD, 256>>>(b0, b1, b2, b3, b4, Bm);
        dwt_kernel<<<BROWS, 256>>>(x, Cm);
    }

    // GEMM: 3 exact full waves (888 CTAs), then one short wave of 272 half-tiles
    gemm_tmpl<4><<<FULL_TILES, 256, SMEM4>>>(Cm, Bm, out);
    gemm_tmpl<2><<<(1024 - FULL_TILES) * 2, 256, SMEM2>>>(Cm, Bm, out);
}

// round 17
// speedup vs baseline: 1.5914x; 1.5914x over previous
#include <cuda_runtime.h>
#include <cuda_fp16.h>
#include <cstdint>

// ---------------- problem constants ----------------
#define BROWS 4096
#define NOUT  4096
#define KTOT  4122
#define KPAD  4160            // 65 * 64

#define OFF_CD4 262
#define OFF_CD3 524
#define OFF_CD2 1042
#define OFF_CD1 2071

// ---------------- scratch (device globals; no allocs allowed) ----------------
__device__ __half g_C[(size_t)BROWS * KPAD];   // coeffs [M, K] row-major fp16
__device__ __half g_B[(size_t)KPAD * NOUT];    // stacked bases [K, N] row-major fp16

__constant__ float c_lo[8] = {
    -0.010597401784997278f,  0.032883011666982945f,  0.030841381835986965f,
    -0.18703481171888114f,  -0.02798376941698385f,   0.6308807679295904f,
     0.7148465705525415f,    0.23037781330885523f };
__constant__ float c_hi[8] = {
    -0.23037781330885523f,   0.7148465705525415f,   -0.6308807679295904f,
    -0.02798376941698385f,   0.18703481171888114f,   0.030841381835986965f,
    -0.032883011666982945f, -0.010597401784997278f };

// ============ fused prologue, role-interleaved per wave ============
// even bid -> DWT row (pair index), odd bid -> B-pack row; 64 spare even bids
// carry the pack-row overflow so each scheduler wave mixes both resource profiles.
// DWT (pywt 'symmetric'): out[j] = sum_m filt[m] * E[8+2j-m],
//   E[i] = a[6-i] (i<7), a[i-7] (i<Nin+7), a[2*Nin+6-i] otherwise.
__global__ void __launch_bounds__(256)
prologue_kernel(const float* __restrict__ x,
                const float* __restrict__ b0, const float* __restrict__ b1,
                const float* __restrict__ b2, const float* __restrict__ b3,
                const float* __restrict__ b4,
                __half* __restrict__ C, __half* __restrict__ Bh)
{
    __shared__ __align__(16) float bufA[4096];
    __shared__ __align__(16) float bufB[2051];

    const int bid  = blockIdx.x;           // 0 .. 8255
    const int tid  = threadIdx.x;
    const int pair = bid >> 1;
    const bool odd = bid & 1;

    bool doDwt = false;
    int row = 0, k = 0;
    if (!odd) {
        if (pair < BROWS) { doDwt = true; row = pair; }
        else              { k = 4128 + (pair - BROWS); }   // 32 overflow pack rows
    } else {
        k = pair;                                          // 0..4127
    }

    if (doDwt) {
        // ---------------- DWT branch ----------------
        const float* xr = x + (size_t)row * 4096;
        __half* Crow = C + (size_t)row * KPAD;

        const float4* x4 = (const float4*)xr;
        float4* bA4 = (float4*)bufA;
#pragma unroll
        for (int i = 0; i < 4; i++) bA4[tid + i * 256] = x4[tid + i * 256];

        for (int c = KTOT + tid; c < KPAD; c += 256) Crow[c] = __float2half_rn(0.f);
        __syncthreads();

        const int nin[4]  = {4096, 2051, 1029, 518};
        const int nout[4] = {2051, 1029, 518, 262};
        const int offD[4] = {OFF_CD1, OFF_CD2, OFF_CD3, OFF_CD4};

        float* src = bufA;
        float* dst = bufB;
#pragma unroll 1
        for (int lv = 0; lv < 4; lv++) {
            const int Nin = nin[lv], Nout = nout[lv];
            const int jIntHi = (Nin - 2) >> 1;
            for (int j = tid; j < Nout; j += 256) {
                float sLo = 0.f, sHi = 0.f;
                if (j >= 4 && j <= jIntHi) {
                    // interior: 4 x float2 loads, FMA order identical to reference
                    const float2* q = (const float2*)(src + 2 * j - 6);
                    const float2 w3 = q[3], w2 = q[2], w1 = q[1], w0 = q[0];
                    sLo = fmaf(c_lo[0], w3.y, sLo); sHi = fmaf(c_hi[0], w3.y, sHi);
                    sLo = fmaf(c_lo[1], w3.x, sLo); sHi = fmaf(c_hi[1], w3.x, sHi);
                    sLo = fmaf(c_lo[2], w2.y, sLo); sHi = fmaf(c_hi[2], w2.y, sHi);
                    sLo = fmaf(c_lo[3], w2.x, sLo); sHi = fmaf(c_hi[3], w2.x, sHi);
                    sLo = fmaf(c_lo[4], w1.y, sLo); sHi = fmaf(c_hi[4], w1.y, sHi);
                    sLo = fmaf(c_lo[5], w1.x, sLo); sHi = fmaf(c_hi[5], w1.x, sHi);
                    sLo = fmaf(c_lo[6], w0.y, sLo); sHi = fmaf(c_hi[6], w0.y, sHi);
                    sLo = fmaf(c_lo[7], w0.x, sLo); sHi = fmaf(c_hi[7], w0.x, sHi);
                } else {
#pragma unroll
                    for (int m = 0; m < 8; m++) {
                        const int i = 8 + 2 * j - m;
                        int idx;
                        if (i < 7)            idx = 6 - i;
                        else if (i < Nin + 7) idx = i - 7;
                        else                  idx = 2 * Nin + 6 - i;
                        const float v = src[idx];
                        sLo = fmaf(c_lo[m], v, sLo);
                        sHi = fmaf(c_hi[m], v, sHi);
                    }
                }
                Crow[offD[lv] + j] = __float2half_rn(sHi);
                if (lv < 3) dst[j] = sLo;
                else        Crow[j] = __float2half_rn(sLo);   // cA4 at col 0
            }
            __syncthreads();
            float* tmp = src; src = dst; dst = tmp;
        }
    } else {
        // ---------------- pack branch: one K-row of Bh per block ----------------
        const float* src = nullptr; int r = 0;
        if      (k < OFF_CD4) { src = b0; r = k; }
        else if (k < OFF_CD3) { src = b1; r = k - OFF_CD4; }
        else if (k < OFF_CD2) { src = b2; r = k - OFF_CD3; }
        else if (k < OFF_CD1) { src = b3; r = k - OFF_CD2; }
        else if (k < KTOT)    { src = b4; r = k - OFF_CD1; }

        __half* dstRow = Bh + (size_t)k * NOUT;
        if (src) {
            const float4* srow = (const float4*)(src + (size_t)r * NOUT);
            float4 v[4];
#pragma unroll
            for (int i = 0; i < 4; i++) v[i] = srow[tid + i * 256];
#pragma unroll
            for (int i = 0; i < 4; i++) {
                __half2 h[2];
                h[0] = __floats2half2_rn(v[i].x, v[i].y);
                h[1] = __floats2half2_rn(v[i].z, v[i].w);
                *(uint64_t*)(dstRow + (tid + i * 256) * 4) = *(uint64_t*)h;
            }
        } else {
#pragma unroll
            for (int i = 0; i < 4; i++)
                *(uint64_t*)(dstRow + (tid + i * 256) * 4) = 0ull;
        }
    }
}

// ---------------- GEMM: [4096,4160] x [4160,4096] fp16 -> fp32 ----------------
// mma.sync.m16n8k16 + ldmatrix + 3-stage cp.async, BK=64, 2 CTAs/SM.
// CTA tile 128x128, 256 threads, 8 warps as 2(m) x 4(n), warp tile 64x32.
// (ncu: tensor=77%, within ~5% of structural floor — FROZEN, do not refactor.)
#define BM 128
#define BN 128
#define BK 64
#define STAGES 3
#define A_STAGE_BYTES 16384     // 128 rows x 64 halves (128B rows)
#define B_STAGE_BYTES 16384     // 64 rows x 128 halves (256B rows)
#define STAGE_BYTES   32768
#define SMEM_BYTES    (STAGES * STAGE_BYTES)   // 98304

__device__ __forceinline__ uint32_t aswz(int r, int chunk) {
    return (uint32_t)(r * 128 + ((chunk ^ (r & 7)) << 4));
}
__device__ __forceinline__ uint32_t bswz(int r, int chunk) {
    return (uint32_t)(r * 256 + (((chunk & 8) | ((chunk ^ r) & 7)) << 4));
}

__device__ __forceinline__ void cp16(uint32_t saddr, const void* gaddr) {
    asm volatile("cp.async.cg.shared.global [%0], [%1], 16;\n" :: "r"(saddr), "l"(gaddr));
}
__device__ __forceinline__ void ldsm4(uint32_t* r, uint32_t addr) {
    asm volatile("ldmatrix.sync.aligned.m8n8.x4.shared.b16 {%0,%1,%2,%3}, [%4];"
                 : "=r"(r[0]), "=r"(r[1]), "=r"(r[2]), "=r"(r[3]) : "r"(addr));
}
__device__ __forceinline__ void ldsm4t(uint32_t* r, uint32_t addr) {
    asm volatile("ldmatrix.sync.aligned.m8n8.x4.trans.shared.b16 {%0,%1,%2,%3}, [%4];"
                 : "=r"(r[0]), "=r"(r[1]), "=r"(r[2]), "=r"(r[3]) : "r"(addr));
}
__device__ __forceinline__ void mma16816(float* c, const uint32_t* a, uint32_t b0, uint32_t b1) {
    asm volatile("mma.sync.aligned.m16n8k16.row.col.f32.f16.f16.f32 "
                 "{%0,%1,%2,%3}, {%4,%5,%6,%7}, {%8,%9}, {%0,%1,%2,%3};"
                 : "+f"(c[0]), "+f"(c[1]), "+f"(c[2]), "+f"(c[3])
                 : "r"(a[0]), "r"(a[1]), "r"(a[2]), "r"(a[3]), "r"(b0), "r"(b1));
}

__global__ void __launch_bounds__(256, 2)
gemm_kernel(const __half* __restrict__ A, const __half* __restrict__ Bm,
            float* __restrict__ Cout)
{
    constexpr int K = KPAD, N = NOUT;
    extern __shared__ char smem[];
    const uint32_t sbase = (uint32_t)__cvta_generic_to_shared(smem);

    const int tid = threadIdx.x;
    const int wid = tid >> 5, lid = tid & 31;
    const int wm  = wid & 1;
    const int wn  = wid >> 1;
    const int rowBase = blockIdx.y * BM;
    const int colBase = blockIdx.x * BN;

    const int l15 = lid & 15, lc = lid >> 4;

    int aR[4]; uint32_t aS[4];
#pragma unroll
    for (int i = 0; i < 4; i++) {
        const int idx = i * 256 + tid;
        aR[i] = idx >> 3;
        aS[i] = aswz(aR[i], idx & 7);
    }
    int bR[4]; uint32_t bS[4];
#pragma unroll
    for (int i = 0; i < 4; i++) {
        const int idx = i * 256 + tid;
        bR[i] = idx >> 4;
        bS[i] = bswz(bR[i], idx & 15);
    }

    const __half* Ag = A + (size_t)rowBase * K;
    const __half* Bg = Bm + colBase;

    uint32_t aBase[4]; int aX[4];
#pragma unroll
    for (int i = 0; i < 4; i++) {
        const int r = wm * 64 + i * 16 + l15;
        aBase[i] = (uint32_t)(r * 128);
        aX[i] = r & 7;
    }
    int bChunk[2] = { wn * 4 + 0 * 2 + lc, wn * 4 + 1 * 2 + lc };

    auto issue_stage = [&](int t, int slot) {
        const int kb = t * BK;
        const uint32_t sa = sbase + slot * STAGE_BYTES;
        const uint32_t sb = sa + A_STAGE_BYTES;
#pragma unroll
        for (int i = 0; i < 4; i++) {
            const int idx = i * 256 + tid;
            cp16(sa + aS[i], Ag + (size_t)aR[i] * K + kb + (idx & 7) * 8);
        }
#pragma unroll
        for (int i = 0; i < 4; i++) {
            const int idx = i * 256 + tid;
            cp16(sb + bS[i], Bg + (size_t)(kb + bR[i]) * N + (idx & 15) * 8);
        }
        asm volatile("cp.async.commit_group;\n" ::: "memory");
    };

    float acc[4][4][4];
#pragma unroll
    for (int i = 0; i < 4; i++)
#pragma unroll
        for (int j = 0; j < 4; j++)
#pragma unroll
            for (int q = 0; q < 4; q++) acc[i][j][q] = 0.f;

    constexpr int NT = K / BK;    // 65
    issue_stage(0, 0);
    issue_stage(1, 1);

    int cs = 0, ps = 2;
    for (int t = 0; t < NT; t++) {
        asm volatile("cp.async.wait_group 1;\n" ::: "memory");
        __syncthreads();
        if (t + 2 < NT) issue_stage(t + 2, ps);

        const uint32_t sa = sbase + cs * STAGE_BYTES;
        const uint32_t sb = sa + A_STAGE_BYTES;

#pragma unroll
        for (int ks = 0; ks < 4; ks++) {
            uint32_t af[4][4], bf[2][4];
#pragma unroll
            for (int i = 0; i < 4; i++)
                ldsm4(af[i], sa + aBase[i] + (uint32_t)((((ks * 2 + lc) ^ aX[i]) << 4)));
#pragma unroll
            for (int g = 0; g < 2; g++) {
                const int r = ks * 16 + l15;
                ldsm4t(bf[g], sb + (uint32_t)(r * 256 +
                        (((bChunk[g] & 8) | ((bChunk[g] ^ r) & 7)) << 4)));
            }
#pragma unroll
            for (int i = 0; i < 4; i++)
#pragma unroll
                for (int j = 0; j < 4; j++)
                    mma16816(acc[i][j], af[i], bf[j >> 1][(j & 1) * 2],
                             bf[j >> 1][(j & 1) * 2 + 1]);
        }
        cs = (cs == STAGES - 1) ? 0 : cs + 1;
        ps = (ps == STAGES - 1) ? 0 : ps + 1;
    }

    // ---- epilogue: fragment -> gmem, streaming stores (keep A/B in L2) ----
    const int er = lid >> 2, ec = (lid & 3) * 2;
#pragma unroll
    for (int i = 0; i < 4; i++) {
        const int row0 = rowBase + wm * 64 + i * 16 + er;
#pragma unroll
        for (int j = 0; j < 4; j++) {
            const int col = colBase + wn * 32 + j * 8 + ec;
            float2* p0 = (float2*)(Cout + (size_t)row0 * N + col);
            float2* p1 = (float2*)(Cout + (size_t)(row0 + 8) * N + col);
            __stcs(p0, make_float2(acc[i][j][0], acc[i][j][1]));
            __stcs(p1, make_float2(acc[i][j][2], acc[i][j][3]));
        }
    }
}

// ---------------- launch ----------------
extern "C" void kernel_launch(void* const* d_in, const int* in_sizes, int n_in,
                              void* d_out, int out_size)
{
    const float* x  = (const float*)d_in[0];
    const float* b0 = (const float*)d_in[1];
    const float* b1 = (const float*)d_in[2];
    const float* b2 = (const float*)d_in[3];
    const float* b3 = (const float*)d_in[4];
    const float* b4 = (const float*)d_in[5];
    float* out = (float*)d_out;

    __half *Cm, *Bm;
    cudaGetSymbolAddress((void**)&Cm, g_C);
    cudaGetSymbolAddress((void**)&Bm, g_B);

    cudaFuncSetAttribute(gemm_kernel,
                         cudaFuncAttributeMaxDynamicSharedMemorySize, SMEM_BYTES);

    prologue_kernel<<<BROWS + KPAD, 256>>>(x, b0, b1, b2, b3, b4, Cm, Bm);
    gemm_kernel<<<dim3(NOUT / BN, BROWS / BM), 256, SMEM_BYTES>>>(Cm, Bm, out);
}